// round 14
// baseline (speedup 1.0000x reference)
#include <cuda_runtime.h>
#include <cuda_bf16.h>
#include <math.h>
#include <stdint.h>

#define NB 64
#define NS 512
#define NH 1024
#define NM 26
#define NE 676
#define NR (NB*NM)          // 1664 node rows total
#define NOFF (NM-1)         // 25 offsets per batch
#define NST 16              // S tiles of 32 rows
#define KSPLIT 16           // gemm1 K splits

// ---------------- scratch (device globals; no allocation allowed) ----------------
__device__ int   g_off[NB*NOFF];
__device__ int   g_count[NB];
__device__ int   g_rowstart[NB];
__device__ int   g_rowmap[NR];
__device__ int   g_ract;
__device__ __align__(16) float g_cls[NB*NH];
__device__ __align__(16) float g_cdact[NB*NH];
__device__ __align__(16) float g_g1p[KSPLIT*NB*2048];  // gemm1 split-K partials
__device__ __align__(16) float g_part[NB*NST*NM*NH];   // segment tile partials
__device__ __align__(16) float g_ND[NR*NH];            // tanh(node_full @ W_nd + b_nd)
__device__ __align__(16) float g_A[NR*NH];             // node_full @ (W1+W3) + b_ed
__device__ __align__(16) float g_Bm[NR*NH];            // node_full @ (W2-W3)
__device__ float g_cvec[2];   // edge logits of all-zero edge row
__device__ float g_nlc[2];    // node logits of all-zero node row
// bf16 split operands for tensor-core GEMM (COMPACTED rows)
__device__ __align__(16) __nv_bfloat16 g_nodeH[NR*NH];
__device__ __align__(16) __nv_bfloat16 g_nodeL[NR*NH];
__device__ __align__(16) __nv_bfloat16 g_WTh[3072*NH];  // W^T (N-major, K cols), hi
__device__ __align__(16) __nv_bfloat16 g_WTl[3072*NH];  // lo

// ============================================================================
// portable PTX helpers (no sm_103a-only features)
// ============================================================================
__device__ __forceinline__ uint32_t smem_to_u32(const void* p) {
    uint32_t a;
    asm("{ .reg .u64 t; cvta.to.shared.u64 t, %1; cvt.u32.u64 %0, t; }" : "=r"(a) : "l"(p));
    return a;
}
__device__ __forceinline__ void ldsm_x4(uint32_t (&r)[4], uint32_t addr) {
    asm volatile("ldmatrix.sync.aligned.m8n8.x4.shared.b16 {%0,%1,%2,%3}, [%4];"
        : "=r"(r[0]), "=r"(r[1]), "=r"(r[2]), "=r"(r[3]) : "r"(addr));
}
__device__ __forceinline__ void mma16816(float (&c)[4], const uint32_t (&a)[4],
                                         uint32_t b0, uint32_t b1) {
    asm volatile("mma.sync.aligned.m16n8k16.row.col.f32.bf16.bf16.f32 "
        "{%0,%1,%2,%3}, {%4,%5,%6,%7}, {%8,%9}, {%0,%1,%2,%3};"
        : "+f"(c[0]), "+f"(c[1]), "+f"(c[2]), "+f"(c[3])
        : "r"(a[0]), "r"(a[1]), "r"(a[2]), "r"(a[3]), "r"(b0), "r"(b1));
}
__device__ __forceinline__ void cp16(uint32_t dst, const void* src) {
    asm volatile("cp.async.cg.shared.global [%0], [%1], 16;" :: "r"(dst), "l"(src));
}
#define CP_COMMIT() asm volatile("cp.async.commit_group;" ::: "memory")
#define CP_WAIT1()  asm volatile("cp.async.wait_group 1;" ::: "memory")
#define CP_WAIT0()  asm volatile("cp.async.wait_group 0;" ::: "memory")

__device__ __forceinline__ float fast_tanh(float x) {
    float y;
    asm("tanh.approx.f32 %0, %1;" : "=f"(y) : "f"(x));
    return y;
}

// ---------------- small helpers ----------------
__device__ __forceinline__ void block_reduce2_store(float s0, float s1,
                                                    float* o0, float* o1,
                                                    float add0, float add1) {
    __shared__ float red[16];
    #pragma unroll
    for (int o = 16; o > 0; o >>= 1) {
        s0 += __shfl_down_sync(0xffffffffu, s0, o);
        s1 += __shfl_down_sync(0xffffffffu, s1, o);
    }
    int t = threadIdx.x;
    if ((t & 31) == 0) { red[t >> 5] = s0; red[8 + (t >> 5)] = s1; }
    __syncthreads();
    if (t == 0) {
        float a = 0.f, b = 0.f;
        #pragma unroll
        for (int w = 0; w < 8; w++) { a += red[w]; b += red[8 + w]; }
        *o0 = a + add0;
        *o1 = b + add1;
    }
}

// ---------------- kernel: prep_cls (0-63) + consts (64-65) + prefix (66) ----------
__global__ void k_prep0(const float* __restrict__ seq, const int* __restrict__ po,
                        const float* __restrict__ bed, const float* __restrict__ Weo,
                        const float* __restrict__ beo, const float* __restrict__ bnd,
                        const float* __restrict__ Wno, const float* __restrict__ bno) {
    int blk = blockIdx.x, t = threadIdx.x;
    if (blk < NB) {
        int b = blk;
        bool wide = (po[1] == 0 && po[3] == 0);
        int val = 0;
        if (t < NOFF) {
            val = wide ? po[(b * NOFF + t) * 2] : po[b * NOFF + t];
            g_off[b * NOFF + t] = val;
        }
        if (t < 32) {
            unsigned mask = __ballot_sync(0xffffffffu, (t < NOFF) && (val > 0));
            if (t == 0) g_count[b] = __popc(mask);
        }
        ((float4*)(g_cls + (size_t)b * NH))[t] =
            ((const float4*)(seq + (size_t)b * NS * NH))[t];
    } else if (blk < NB + 2) {
        int which = blk - NB;               // 0: edge const, 1: node const
        const float*  bias = which ? bnd : bed;
        const float2* w    = which ? (const float2*)Wno : (const float2*)Weo;
        const float*  b2   = which ? bno : beo;
        float* dstp        = which ? g_nlc : g_cvec;
        float s0 = 0.f, s1 = 0.f;
        for (int h = t; h < NH; h += 256) {
            float v = tanhf(bias[h]);
            float2 ww = w[h];
            s0 += v * ww.x; s1 += v * ww.y;
        }
        block_reduce2_store(s0, s1, &dstp[0], &dstp[1], b2[0], b2[1]);
    } else {
        // prefix + rowmap: recompute counts straight from po (no inter-block dep)
        __shared__ int scnt[NB];
        __shared__ int sstart[NB];
        bool wide = (po[1] == 0 && po[3] == 0);
        if (t < NB) {
            int c = 0;
            #pragma unroll
            for (int m = 0; m < NOFF; m++) {
                int v = wide ? po[(t * NOFF + m) * 2] : po[t * NOFF + m];
                c += (v > 0);
            }
            scnt[t] = c;
        }
        __syncthreads();
        if (t == 0) {
            int acc = 0;
            for (int b = 0; b < NB; b++) {
                sstart[b] = acc;
                g_rowstart[b] = acc;
                acc += scnt[b] + 1;
            }
            g_ract = acc;
        }
        __syncthreads();
        for (int i = t; i < NR; i += 256) g_rowmap[i] = -1;
        __syncthreads();
        for (int i = t; i < NB * NM; i += 256) {
            int b = i / NM, m = i - b * NM;
            if (m <= scnt[b]) g_rowmap[sstart[b] + m] = i;
        }
    }
}

// ---------------- kernel: segment partial sums, contiguous full rows ----------------
__global__ void k_segsum(const float* __restrict__ seq) {
    int st = blockIdx.x;          // 0..15
    int b  = blockIdx.y;          // 0..63
    int t  = threadIdx.x;         // 0..255 (full row, float4 each)
    int s0 = st * 32;
    int sEnd = s0 + 31;
    int cnt = g_count[b];
    if (s0 > g_off[b * NOFF + cnt - 1]) return;   // past the last segment: no work
    const float4* base = (const float4*)(seq + (size_t)b * NS * NH) + t;
    int prev = 0;
    for (int m = 0; m < cnt; m++) {
        int off = g_off[b * NOFF + m];
        int lo = prev + 1;
        if (lo < s0) lo = s0;
        int hi = off < sEnd ? off : sEnd;
        if (lo <= hi) {
            float4 a0 = make_float4(0.f,0.f,0.f,0.f), a1 = a0, a2 = a0, a3 = a0;
            int s = lo;
            for (; s + 3 <= hi; s += 4) {
                float4 v0 = base[(size_t)(s + 0) * 256];
                float4 v1 = base[(size_t)(s + 1) * 256];
                float4 v2 = base[(size_t)(s + 2) * 256];
                float4 v3 = base[(size_t)(s + 3) * 256];
                a0.x += v0.x; a0.y += v0.y; a0.z += v0.z; a0.w += v0.w;
                a1.x += v1.x; a1.y += v1.y; a1.z += v1.z; a1.w += v1.w;
                a2.x += v2.x; a2.y += v2.y; a2.z += v2.z; a2.w += v2.w;
                a3.x += v3.x; a3.y += v3.y; a3.z += v3.z; a3.w += v3.w;
            }
            for (; s <= hi; s++) {
                float4 v = base[(size_t)s * 256];
                a0.x += v.x; a0.y += v.y; a0.z += v.z; a0.w += v.w;
            }
            a0.x += a1.x + a2.x + a3.x;
            a0.y += a1.y + a2.y + a3.y;
            a0.z += a1.z + a2.z + a3.z;
            a0.w += a1.w + a2.w + a3.w;
            ((float4*)(g_part + (((size_t)(b * NST + st) * NM) + m) * NH))[t] = a0;
        }
        prev = off;
        if (prev >= sEnd) break;
    }
}

// ---------------- kernel: GEMM1 split-K partial ----------
__global__ __launch_bounds__(256) void k_gemm1p(const float* __restrict__ Wnaf,
                                                const float* __restrict__ Wcd) {
    __shared__ float Xs[64 * 68];      // [k][m], pad 4
    __shared__ float Ws[64 * 64];      // [k][n]
    int n0 = blockIdx.x * 64;                 // 0..2047
    int ks0 = blockIdx.y * 64;                // K chunk start
    const float* W = (n0 < 1024) ? Wnaf : Wcd;
    int nc0 = (n0 < 1024) ? n0 : n0 - 1024;
    int t = threadIdx.x;
    #pragma unroll
    for (int r = 0; r < 4; r++) {
        int f4 = t + r * 256;
        int row = f4 >> 4, q = f4 & 15;
        float4 x = *(const float4*)(g_cls + (size_t)row * NH + ks0 + q * 4);
        Xs[(q * 4 + 0) * 68 + row] = x.x;
        Xs[(q * 4 + 1) * 68 + row] = x.y;
        Xs[(q * 4 + 2) * 68 + row] = x.z;
        Xs[(q * 4 + 3) * 68 + row] = x.w;
        float4 w = *(const float4*)(W + (size_t)(ks0 + row) * 1024 + nc0 + q * 4);
        *(float4*)(Ws + row * 64 + q * 4) = w;
    }
    __syncthreads();
    int tx = t & 15, ty = t >> 4;
    float acc[4][4] = {};
    #pragma unroll 16
    for (int k = 0; k < 64; k++) {
        float a[4], bb[4];
        *(float4*)a  = *(const float4*)(Xs + k * 68 + ty * 4);
        *(float4*)bb = *(const float4*)(Ws + k * 64 + tx * 4);
        #pragma unroll
        for (int i = 0; i < 4; i++)
            #pragma unroll
            for (int j = 0; j < 4; j++)
                acc[i][j] += a[i] * bb[j];
    }
    float* dst = g_g1p + (size_t)blockIdx.y * NB * 2048;
    #pragma unroll
    for (int i = 0; i < 4; i++) {
        int m = ty * 4 + i;
        #pragma unroll
        for (int j = 0; j < 4; j++)
            dst[(size_t)m * 2048 + n0 + tx * 4 + j] = acc[i][j];
    }
}

// ---------------- kernel: GEMM1 reduce, cdact half only (off critical path) --------
__global__ void k_gemm1r_cd(const float* __restrict__ bcd) {
    int idx = blockIdx.x * 256 + threadIdx.x;   // 0 .. 64*1024-1
    int m = idx >> 10, c = idx & 1023;
    float s = 0.f;
    #pragma unroll
    for (int ks = 0; ks < KSPLIT; ks++)
        s += g_g1p[(size_t)ks * NB * 2048 + m * 2048 + 1024 + c];
    g_cdact[(size_t)m * NH + c] = tanhf(s + bcd[c]);
}

// ---------------- kernel: W^T build + bf16 split ----------------
__global__ void k_prep_weights(const float* __restrict__ Wnd,
                               const float* __restrict__ Wed) {
    __shared__ float tile[32][33];
    int n0 = blockIdx.x * 32;
    int k0 = blockIdx.y * 32;
    int tx = threadIdx.x, ty = threadIdx.y;
    #pragma unroll
    for (int kk = 0; kk < 32; kk += 8) {
        int k = k0 + kk + ty;
        int n = n0 + tx;
        float v;
        if (n < 1024) v = Wnd[(size_t)k * 1024 + n];
        else if (n < 2048) { int c = n - 1024; v = Wed[(size_t)k * 1024 + c] + Wed[(size_t)(2048 + k) * 1024 + c]; }
        else { int c = n - 2048; v = Wed[(size_t)(1024 + k) * 1024 + c] - Wed[(size_t)(2048 + k) * 1024 + c]; }
        tile[kk + ty][tx] = v;
    }
    __syncthreads();
    #pragma unroll
    for (int kk = 0; kk < 32; kk += 8) {
        int n = n0 + kk + ty;
        int k = k0 + tx;
        float v = tile[tx][kk + ty];
        __nv_bfloat16 h = __float2bfloat16(v);
        g_WTh[(size_t)n * NH + k] = h;
        g_WTl[(size_t)n * NH + k] = __float2bfloat16(v - __bfloat162float(h));
    }
}

// ---------------- kernel: finalize node rows (naf reduced inline), bf16 split ------
__global__ void k_finalize(const float* __restrict__ bnaf) {
    int m = blockIdx.x, b = blockIdx.y, t = threadIdx.x;
    int cnt = g_count[b];
    if (m > cnt) return;
    float4 o = make_float4(0.f, 0.f, 0.f, 0.f);
    if (m < cnt) {
        int off  = g_off[b * NOFF + m];
        int prev = (m == 0) ? 0 : g_off[b * NOFF + m - 1];
        int stLo = (prev + 1) >> 5, stHi = off >> 5;
        for (int st = stLo; st <= stHi; st++) {
            float4 p = ((const float4*)(g_part + (((size_t)(b * NST + st) * NM) + m) * NH))[t];
            o.x += p.x; o.y += p.y; o.z += p.z; o.w += p.w;
        }
        float sc = 1.f / (float)(off - prev);
        o.x *= sc; o.y *= sc; o.z *= sc; o.w *= sc;
    } else {
        // naf row: reduce gemm1 split-K partials directly (cols 0..1023)
        #pragma unroll
        for (int ks = 0; ks < KSPLIT; ks++) {
            float4 p = *(const float4*)(g_g1p + (size_t)ks * NB * 2048 + b * 2048 + t * 4);
            o.x += p.x; o.y += p.y; o.z += p.z; o.w += p.w;
        }
        float4 bn = *(const float4*)(bnaf + t * 4);
        o.x += bn.x; o.y += bn.y; o.z += bn.z; o.w += bn.w;
    }
    size_t row = (size_t)(g_rowstart[b] + m);
    __nv_bfloat16 h0 = __float2bfloat16(o.x), h1 = __float2bfloat16(o.y);
    __nv_bfloat16 h2 = __float2bfloat16(o.z), h3 = __float2bfloat16(o.w);
    __nv_bfloat16 l0 = __float2bfloat16(o.x - __bfloat162float(h0));
    __nv_bfloat16 l1 = __float2bfloat16(o.y - __bfloat162float(h1));
    __nv_bfloat16 l2 = __float2bfloat16(o.z - __bfloat162float(h2));
    __nv_bfloat16 l3 = __float2bfloat16(o.w - __bfloat162float(h3));
    __nv_bfloat162 hA = __halves2bfloat162(h0, h1), hB = __halves2bfloat162(h2, h3);
    __nv_bfloat162 lA = __halves2bfloat162(l0, l1), lB = __halves2bfloat162(l2, l3);
    uint2 hv, lv;
    hv.x = *(uint32_t*)&hA; hv.y = *(uint32_t*)&hB;
    lv.x = *(uint32_t*)&lA; lv.y = *(uint32_t*)&lB;
    ((uint2*)(g_nodeH + row * NH))[t] = hv;
    ((uint2*)(g_nodeL + row * NH))[t] = lv;
}

// ============================================================================
// HMMA GEMM on COMPACTED rows, M-tile 64. CTA 64x128, K-tile 32, 3-stage
// cp.async, 24KB/stage (72KB -> 3 CTA/SM). 8 warps (2m x 4n), warp 32x32.
// nxoff selects the n-tile window: 0..7 = ND section, 8..23 = A/B sections.
// ============================================================================
#define TB_A 4096
#define TB_B 8192
#define STG_B 24576
#define GEMM_SMEM (3*STG_B)

__global__ __launch_bounds__(256, 3) void k_mmagemm(const float* __restrict__ bnd,
                                                    const float* __restrict__ bed,
                                                    int nxoff) {
    const int m0 = blockIdx.y * 64, n0 = (blockIdx.x + nxoff) * 128;
    if (m0 >= g_ract) return;
    extern __shared__ char smem[];
    uint32_t sb = smem_to_u32(smem);
    const int t = threadIdx.x;
    const int lane = t & 31, wid = t >> 5;
    const int wm = wid >> 2, wn = wid & 3;

    uint32_t rA = (uint32_t)t >> 2, cA = (uint32_t)t & 3;
    uint32_t oA = rA * 64 + cA * 16;
    uint32_t swoA = oA ^ ((oA >> 3) & 0x30);
    uint32_t gA = (uint32_t)(m0 + rA) * NH + cA * 8;
    uint32_t swoB[2], gB[2];
    #pragma unroll
    for (int j = 0; j < 2; j++) {
        int u = j * 256 + t;
        uint32_t rB = (uint32_t)u >> 2, cB = (uint32_t)u & 3;
        uint32_t o = rB * 64 + cB * 16;
        swoB[j] = o ^ ((o >> 3) & 0x30);
        gB[j] = (uint32_t)(n0 + rB) * NH + cB * 8;
    }

    auto issue = [&](int kc) {
        uint32_t kk = (uint32_t)kc * 32;
        uint32_t d = sb + (kc % 3) * STG_B;
        cp16(d + swoA,        g_nodeH + gA + kk);
        cp16(d + TB_A + swoA, g_nodeL + gA + kk);
        #pragma unroll
        for (int j = 0; j < 2; j++) {
            cp16(d + 2 * TB_A + swoB[j],        g_WTh + gB[j] + kk);
            cp16(d + 2 * TB_A + TB_B + swoB[j], g_WTl + gB[j] + kk);
        }
        CP_COMMIT();
    };

    float acc[2][4][4] = {};

    const uint32_t aRow = (uint32_t)(wm * 32 + (lane & 15));
    const uint32_t aKhalf = (uint32_t)((lane >> 4) * 16);
    const uint32_t bRowBase = (uint32_t)(wn * 32 + ((lane >> 4) & 1) * 8 + (lane & 7));
    const uint32_t bCol = (uint32_t)(((lane >> 3) & 1) * 16);

    issue(0);
    issue(1);

    for (int kc = 0; kc < 32; kc++) {
        if (kc == 31) { CP_WAIT0(); } else { CP_WAIT1(); }
        __syncthreads();
        if (kc + 2 < 32) issue(kc + 2);
        uint32_t base = sb + (kc % 3) * STG_B;

        #pragma unroll
        for (int ks = 0; ks < 2; ks++) {
            uint32_t bH[2][4], bL[2][4];
            #pragma unroll
            for (int p = 0; p < 2; p++) {
                uint32_t o = (bRowBase + p * 16) * 64 + ks * 32 + bCol;
                o ^= (o >> 3) & 0x30;
                ldsm_x4(bH[p], base + 2 * TB_A + o);
                ldsm_x4(bL[p], base + 2 * TB_A + TB_B + o);
            }
            #pragma unroll
            for (int mt = 0; mt < 2; mt++) {
                uint32_t aH[4], aL[4];
                uint32_t o = (aRow + mt * 16) * 64 + ks * 32 + aKhalf;
                o ^= (o >> 3) & 0x30;
                ldsm_x4(aH, base + o);
                ldsm_x4(aL, base + TB_A + o);
                #pragma unroll
                for (int nt = 0; nt < 4; nt++) {
                    int p = nt >> 1, q = (nt & 1) * 2;
                    mma16816(acc[mt][nt], aH, bH[p][q], bH[p][q + 1]);
                    mma16816(acc[mt][nt], aH, bL[p][q], bL[p][q + 1]);
                    mma16816(acc[mt][nt], aL, bH[p][q], bH[p][q + 1]);
                }
            }
        }
    }

    int sec  = n0 >> 10;
    int ncol = n0 & 1023;
    float* dst = (sec == 0) ? g_ND : ((sec == 1) ? g_A : g_Bm);
    int g = lane >> 2, tq = lane & 3;
    #pragma unroll
    for (int mt = 0; mt < 2; mt++) {
        int m = m0 + wm * 32 + mt * 16 + g;
        int r0 = g_rowmap[m];
        int r1 = g_rowmap[m + 8];
        #pragma unroll
        for (int nt = 0; nt < 4; nt++) {
            int n = ncol + wn * 32 + nt * 8 + tq * 2;
            float2 v0 = make_float2(acc[mt][nt][0], acc[mt][nt][1]);
            float2 v1 = make_float2(acc[mt][nt][2], acc[mt][nt][3]);
            if (sec == 0) {
                float b0 = bnd[n], b1 = bnd[n + 1];
                v0.x = tanhf(v0.x + b0); v0.y = tanhf(v0.y + b1);
                v1.x = tanhf(v1.x + b0); v1.y = tanhf(v1.y + b1);
            } else if (sec == 1) {
                float b0 = bed[n], b1 = bed[n + 1];
                v0.x += b0; v0.y += b1;
                v1.x += b0; v1.y += b1;
            }
            if (r0 >= 0) *(float2*)(dst + (size_t)r0 * NH + n) = v0;
            if (r1 >= 0) *(float2*)(dst + (size_t)r1 * NH + n) = v1;
        }
    }
}

// ---------------- kernel: edge logits, tiled: 8 B-rows in smem, stream A rows ------
__global__ __launch_bounds__(256) void k_edges(const float* __restrict__ Weo,
                                               const float* __restrict__ beo,
                                               float* __restrict__ out) {
    int b = blockIdx.x;           // 0..63
    int it = blockIdx.y;          // 0..3 = i-tiles; 4 = invalid fill
    int t = threadIdx.x, warp = t >> 5, lane = t & 31;
    int n = g_count[b] + 1;
    int nn = n * n;
    float* ob = out + 128 + NR * 2 + (size_t)b * NE * 2;
    if (it == 4) {
        float c0 = g_cvec[0], c1 = g_cvec[1];
        for (int k = nn + t; k < NE; k += 256) {
            ob[k * 2] = c0; ob[k * 2 + 1] = c1;
        }
        return;
    }
    int i0 = it * 8;
    if (i0 >= n) return;
    __shared__ __align__(16) float sB[8][NH];
    __shared__ __align__(16) float sw0[NH];
    __shared__ __align__(16) float sw1[NH];
    for (int h = t; h < NH; h += 256) {
        float2 ww = ((const float2*)Weo)[h];
        sw0[h] = ww.x; sw1[h] = ww.y;
    }
    int nrows = n - i0; if (nrows > 8) nrows = 8;
    for (int u = t; u < nrows * 256; u += 256) {
        int ri = u >> 8, c4 = u & 255;
        ((float4*)sB[ri])[c4] =
            ((const float4*)(g_Bm + (size_t)(b * NM + i0 + ri) * NH))[c4];
    }
    __syncthreads();
    float be0 = beo[0], be1 = beo[1];
    for (int j = warp; j < n; j += 8) {
        const float4* Ar = (const float4*)(g_A + (size_t)(b * NM + j) * NH);
        float s0[8] = {}, s1[8] = {};
        #pragma unroll
        for (int q = 0; q < 8; q++) {            // FULL row: 8*32 = 256 float4
            int h4 = q * 32 + lane;
            float4 a  = Ar[h4];
            float4 w0 = ((const float4*)sw0)[h4];
            float4 w1 = ((const float4*)sw1)[h4];
            #pragma unroll
            for (int i = 0; i < 8; i++) {
                float4 bb = ((const float4*)sB[i])[h4];
                float v0 = fast_tanh(a.x + bb.x);
                float v1 = fast_tanh(a.y + bb.y);
                float v2 = fast_tanh(a.z + bb.z);
                float v3 = fast_tanh(a.w + bb.w);
                s0[i] += v0 * w0.x + v1 * w0.y + v2 * w0.z + v3 * w0.w;
                s1[i] += v0 * w1.x + v1 * w1.y + v2 * w1.z + v3 * w1.w;
            }
        }
        #pragma unroll
        for (int i = 0; i < 8; i++) {
            #pragma unroll
            for (int off = 16; off > 0; off >>= 1) {
                s0[i] += __shfl_down_sync(0xffffffffu, s0[i], off);
                s1[i] += __shfl_down_sync(0xffffffffu, s1[i], off);
            }
            if (lane == 0 && i0 + i < n) {
                int k = (i0 + i) * n + j;
                ob[k * 2]     = s0[i] + be0;
                ob[k * 2 + 1] = s1[i] + be1;
            }
        }
    }
}

// ---------------- kernel: node logits + cls logits (warp per row) ------------------
__global__ __launch_bounds__(256) void k_nodelogits(const float* __restrict__ Wno,
                                                    const float* __restrict__ bno,
                                                    const float* __restrict__ Wco,
                                                    const float* __restrict__ bco,
                                                    float* __restrict__ out) {
    int blk = blockIdx.x, t = threadIdx.x;
    int warp = t >> 5, lane = t & 31;
    const float4* X;
    const float4* W4;
    float add0, add1;
    float* o;
    if (blk < 208) {
        int r = blk * 8 + warp;
        int b = r / NM, m = r - b * NM;
        o = out + 128 + (size_t)r * 2;
        if (m > g_count[b]) {
            if (lane < 2) o[lane] = g_nlc[lane];
            return;
        }
        X = (const float4*)(g_ND + (size_t)r * NH);
        W4 = (const float4*)Wno;
        add0 = bno[0]; add1 = bno[1];
    } else {
        int b = (blk - 208) * 8 + warp;
        o = out + (size_t)b * 2;
        X = (const float4*)(g_cdact + (size_t)b * NH);
        W4 = (const float4*)Wco;
        add0 = bco[0]; add1 = bco[1];
    }
    float s0 = 0.f, s1 = 0.f;
    #pragma unroll
    for (int it = 0; it < 8; it++) {
        int h4 = it * 32 + lane;
        float4 x  = X[h4];
        float4 wa = W4[h4 * 2];
        float4 wb = W4[h4 * 2 + 1];
        s0 += x.x * wa.x + x.y * wa.z + x.z * wb.x + x.w * wb.z;
        s1 += x.x * wa.y + x.y * wa.w + x.z * wb.y + x.w * wb.w;
    }
    #pragma unroll
    for (int off = 16; off > 0; off >>= 1) {
        s0 += __shfl_down_sync(0xffffffffu, s0, off);
        s1 += __shfl_down_sync(0xffffffffu, s1, off);
    }
    if (lane == 0) { o[0] = s0 + add0; o[1] = s1 + add1; }
}

// ---------------- launch: multi-stream fork/join (graph-capture legal) -------------
extern "C" void kernel_launch(void* const* d_in, const int* in_sizes, int n_in,
                              void* d_out, int out_size) {
    const float* seq  = (const float*)d_in[0];
    const int*   po   = (const int*)  d_in[1];
    const float* Wnaf = (const float*)d_in[4];
    const float* bnaf = (const float*)d_in[5];
    const float* Wcd  = (const float*)d_in[6];
    const float* bcd  = (const float*)d_in[7];
    const float* Wco  = (const float*)d_in[8];
    const float* bco  = (const float*)d_in[9];
    const float* Wnd  = (const float*)d_in[10];
    const float* bnd  = (const float*)d_in[11];
    const float* Wno  = (const float*)d_in[12];
    const float* bno  = (const float*)d_in[13];
    const float* Wed  = (const float*)d_in[14];
    const float* bed  = (const float*)d_in[15];
    const float* Weo  = (const float*)d_in[16];
    const float* beo  = (const float*)d_in[17];
    float* out = (float*)d_out;

    static cudaStream_t s1 = nullptr, s2 = nullptr;
    static cudaEvent_t ev0, ev1, ev2, evR, evF, evN;
    if (!s1) {
        cudaFuncSetAttribute(k_mmagemm, cudaFuncAttributeMaxDynamicSharedMemorySize, GEMM_SMEM);
        cudaStreamCreateWithFlags(&s1, cudaStreamNonBlocking);
        cudaStreamCreateWithFlags(&s2, cudaStreamNonBlocking);
        cudaEventCreateWithFlags(&ev0, cudaEventDisableTiming);
        cudaEventCreateWithFlags(&ev1, cudaEventDisableTiming);
        cudaEventCreateWithFlags(&ev2, cudaEventDisableTiming);
        cudaEventCreateWithFlags(&evR, cudaEventDisableTiming);
        cudaEventCreateWithFlags(&evF, cudaEventDisableTiming);
        cudaEventCreateWithFlags(&evN, cudaEventDisableTiming);
    }

    // 1: root (offsets/counts/cls/consts/prefix)
    k_prep0<<<NB + 3, 256>>>(seq, po, bed, Weo, beo, bnd, Wno, bno);
    cudaEventRecord(ev0, 0);

    // 2 (s1): gemm1p -> cdact reduce
    cudaStreamWaitEvent(s1, ev0, 0);
    k_gemm1p<<<dim3(32, KSPLIT), 256, 0, s1>>>(Wnaf, Wcd);
    cudaEventRecord(ev1, s1);
    k_gemm1r_cd<<<256, 256, 0, s1>>>(bcd);
    cudaEventRecord(evR, s1);

    // 3 (s2): weight prep
    cudaStreamWaitEvent(s2, ev0, 0);
    k_prep_weights<<<dim3(96, 32), dim3(32, 8), 0, s2>>>(Wnd, Wed);
    cudaEventRecord(ev2, s2);

    // 4 (legacy): segment sums (contiguous full rows)  <- profiled slot
    k_segsum<<<dim3(NST, NB), 256>>>(seq);

    // 5 (legacy): finalize (needs segsum + gemm1p partials)
    cudaStreamWaitEvent(0, ev1, 0);
    k_finalize<<<dim3(NM, NB), 256>>>(bnaf);
    cudaEventRecord(evF, 0);

    // 6 (legacy): A/B sections of the GEMM (n-tiles 8..23), then tiled edges
    cudaStreamWaitEvent(0, ev2, 0);
    k_mmagemm<<<dim3(16, 26), 256, GEMM_SMEM>>>(bnd, bed, 8);
    k_edges<<<dim3(NB, 5), 256>>>(Weo, beo, out);

    // 7 (s1): ND section (n-tiles 0..7), then node+cls logits (needs cdact in-stream)
    cudaStreamWaitEvent(s1, evF, 0);
    cudaStreamWaitEvent(s1, ev2, 0);
    k_mmagemm<<<dim3(8, 26), 256, GEMM_SMEM, s1>>>(bnd, bed, 0);
    k_nodelogits<<<216, 256, 0, s1>>>(Wno, bno, Wco, bco, out);
    cudaEventRecord(evN, s1);

    // join
    cudaStreamWaitEvent(0, evN, 0);
}